// round 5
// baseline (speedup 1.0000x reference)
#include <cuda_runtime.h>
#include <math.h>

// LogLinearAttention collapses analytically:
//   softmax over axis=1 (s) => sum_s attn[b,s,t] == 1
//   pooled[b,d] = sum_t r[b,t,d]  = (sum_s x[b,s,:]) @ Wr^T + S*br
//   out[b] = sigmoid( sum_d xs[b,d]*u[d] + c ),  u = Wl @ Wr,  c = S*dot(br,Wl)+bl
// Only x (32 MiB) and Wr (1 MiB) matter. HBM-bound streaming pass.

#define BB 8
#define SS 2048
#define DD 512
#define D4 128            // float4 columns per row
#define JCHUNK 4          // Wr rows per block in k0
#define NJB (DD / JCHUNK) // 128
#define ROWS 16           // x rows per block in k1
#define NCHUNK (SS / ROWS)   // 128
#define NPZ (BB * NCHUNK)    // 1024

__device__ float g_pu[NJB * DD];   // partial u per j-chunk
__device__ float g_u[DD];          // u = Wl @ Wr
__device__ float g_pz[NPZ];        // per-(b,chunk) scalar partials

// ---------------------------------------------------------------------------
// k0: partial u[d] = sum_{j in chunk} Wl[j] * Wr[j,d]
// grid 128, block 128 (one float4 column per thread). Coalesced Wr rows.
// ---------------------------------------------------------------------------
__global__ void k0_upartial(const float* __restrict__ Wr,
                            const float* __restrict__ Wl) {
    const int jb = blockIdx.x;
    const int t  = threadIdx.x;
    float4 acc = make_float4(0.f, 0.f, 0.f, 0.f);
#pragma unroll
    for (int jj = 0; jj < JCHUNK; ++jj) {
        const int j = jb * JCHUNK + jj;
        const float wl = __ldg(Wl + j);
        const float4 w = reinterpret_cast<const float4*>(Wr + (size_t)j * DD)[t];
        acc.x = fmaf(wl, w.x, acc.x);
        acc.y = fmaf(wl, w.y, acc.y);
        acc.z = fmaf(wl, w.z, acc.z);
        acc.w = fmaf(wl, w.w, acc.w);
    }
    reinterpret_cast<float4*>(g_pu + (size_t)jb * DD)[t] = acc;
}

// ---------------------------------------------------------------------------
// k0b: u[d] = sum_jb g_pu[jb][d].  1 block, 128 threads, L2-resident.
// ---------------------------------------------------------------------------
__global__ void k0b_ucombine() {
    const int t = threadIdx.x;
    float4 acc = make_float4(0.f, 0.f, 0.f, 0.f);
#pragma unroll 8
    for (int jb = 0; jb < NJB; ++jb) {
        const float4 p = reinterpret_cast<const float4*>(g_pu + (size_t)jb * DD)[t];
        acc.x += p.x; acc.y += p.y; acc.z += p.z; acc.w += p.w;
    }
    reinterpret_cast<float4*>(g_u)[t] = acc;
}

// ---------------------------------------------------------------------------
// k1: the 32 MiB pass.  grid 1024 (b * 128 chunks of 16 rows), block 128.
// Each thread: 16 independent float4 loads (MLP=16) dotted with u, then a
// fixed shfl/smem tree reduction -> g_pz[blk].  Pure HBM streaming.
// ---------------------------------------------------------------------------
__global__ void __launch_bounds__(128) k1_xdot(const float* __restrict__ x) {
    const int blk = blockIdx.x;
    const int b   = blk / NCHUNK;
    const int ch  = blk % NCHUNK;
    const int t   = threadIdx.x;

    const float4 uv = reinterpret_cast<const float4*>(g_u)[t];
    const float4* xp = reinterpret_cast<const float4*>(
        x + ((size_t)b * SS + (size_t)ch * ROWS) * DD);

    float4 acc = make_float4(0.f, 0.f, 0.f, 0.f);
#pragma unroll
    for (int r = 0; r < ROWS; ++r) {
        const float4 v = xp[(size_t)r * D4 + t];
        acc.x = fmaf(v.x, uv.x, acc.x);
        acc.y = fmaf(v.y, uv.y, acc.y);
        acc.z = fmaf(v.z, uv.z, acc.z);
        acc.w = fmaf(v.w, uv.w, acc.w);
    }
    float s = (acc.x + acc.y) + (acc.z + acc.w);

#pragma unroll
    for (int off = 16; off > 0; off >>= 1)
        s += __shfl_xor_sync(0xffffffffu, s, off);

    __shared__ float red[4];
    if ((t & 31) == 0) red[t >> 5] = s;
    __syncthreads();
    if (t == 0) g_pz[blk] = (red[0] + red[1]) + (red[2] + red[3]);
}

// ---------------------------------------------------------------------------
// k2: out[b] = sigmoid( sum_chunks g_pz[b,*] + S*dot(br,Wl) + bl )
// 1 block, 256 threads. Warp w handles batch w.
// ---------------------------------------------------------------------------
__global__ void k2_final(const float* __restrict__ br,
                         const float* __restrict__ Wl,
                         const float* __restrict__ bl,
                         float* __restrict__ out) {
    __shared__ float sdot[8];
    __shared__ float sc;
    const int t = threadIdx.x;

    // dot(br, Wl) over 512 elements with 256 threads
    float p = br[t] * Wl[t] + br[t + 256] * Wl[t + 256];
#pragma unroll
    for (int off = 16; off > 0; off >>= 1)
        p += __shfl_xor_sync(0xffffffffu, p, off);
    if ((t & 31) == 0) sdot[t >> 5] = p;
    __syncthreads();
    if (t == 0) {
        float d = 0.f;
#pragma unroll
        for (int i = 0; i < 8; ++i) d += sdot[i];
        sc = (float)SS * d + bl[0];
    }
    __syncthreads();

    const int w = t >> 5, lane = t & 31;
    if (w < BB) {
        float z = 0.f;
#pragma unroll
        for (int i = lane; i < NCHUNK; i += 32) z += g_pz[w * NCHUNK + i];
#pragma unroll
        for (int off = 16; off > 0; off >>= 1)
            z += __shfl_xor_sync(0xffffffffu, z, off);
        if (lane == 0) {
            const float zz = z + sc;
            out[w] = 1.0f / (1.0f + expf(-zz));
        }
    }
}

// ---------------------------------------------------------------------------
// Inputs (metadata order): 0=x 1=Wq 2=bq 3=Wv 4=bv 5=Wr 6=br 7=Wl 8=bl
// Output: float32 [B] (= [B,1])
// ---------------------------------------------------------------------------
extern "C" void kernel_launch(void* const* d_in, const int* in_sizes, int n_in,
                              void* d_out, int out_size) {
    const float* x  = (const float*)d_in[0];
    const float* Wr = (const float*)d_in[5];
    const float* br = (const float*)d_in[6];
    const float* Wl = (const float*)d_in[7];
    const float* bl = (const float*)d_in[8];
    float* out = (float*)d_out;

    k0_upartial<<<NJB, 128>>>(Wr, Wl);
    k0b_ucombine<<<1, 128>>>();
    k1_xdot<<<NPZ, 128>>>(x);
    k2_final<<<1, 256>>>(br, Wl, bl, out);
}